// round 2
// baseline (speedup 1.0000x reference)
#include <cuda_runtime.h>
#include <math.h>

#define Bn 32768
#define Tn 16

// ---------------- device scratch (no allocation allowed) ----------------
__device__ float g_feat[Bn * 128];
__device__ float g_h1[Bn * 128];
__device__ float g_c1[Bn * 128];
__device__ float g_h2[Bn * 128];
__device__ float g_c2[Bn * 128];
__device__ float g_W1t[384 * 512];   // rows 0..255: w_ih1 dims, 256..383: w_hh1 dims
__device__ float g_W2t[256 * 512];   // rows 0..127: w_ih2 dims, 128..255: w_hh2 dims
__device__ float g_b1[512];
__device__ float g_b2[512];

__device__ __forceinline__ float sigf(float x) { return 1.0f / (1.0f + expf(-x)); }
__device__ __forceinline__ float eluf(float x) { return x > 0.0f ? x : expm1f(x); }

// ---------------- weight prep: transpose to [K][512], fuse biases ----------------
__global__ void prep_kernel(const float* __restrict__ w_ih1, const float* __restrict__ w_hh1,
                            const float* __restrict__ b_ih1, const float* __restrict__ b_hh1,
                            const float* __restrict__ w_ih2, const float* __restrict__ w_hh2,
                            const float* __restrict__ b_ih2, const float* __restrict__ b_hh2) {
    int i = blockIdx.x * blockDim.x + threadIdx.x;
    const int total1 = 384 * 512;
    const int total2 = 256 * 512;
    if (i < total1) {
        int k = i >> 9, n = i & 511;
        g_W1t[i] = (k < 256) ? w_ih1[n * 256 + k] : w_hh1[n * 128 + (k - 256)];
    } else if (i < total1 + total2) {
        int i2 = i - total1;
        int k = i2 >> 9, n = i2 & 511;
        g_W2t[i2] = (k < 128) ? w_ih2[n * 128 + k] : w_hh2[n * 128 + (k - 128)];
    } else if (i < total1 + total2 + 512) {
        int n = i - total1 - total2;
        g_b1[n] = b_ih1[n] + b_hh1[n];
    } else if (i < total1 + total2 + 1024) {
        int n = i - total1 - total2 - 512;
        g_b2[n] = b_ih2[n] + b_hh2[n];
    }
}

// ---------------- fused conv stack: x[B,1,19] -> feat[B,128] ----------------
// Block: 256 threads, 16 batch elements. Everything staged in dynamic smem.
__launch_bounds__(256)
__global__ void conv_kernel(const float* __restrict__ x,
                            const float* __restrict__ w1, const float* __restrict__ b1,
                            const float* __restrict__ w2, const float* __restrict__ b2,
                            const float* __restrict__ w3, const float* __restrict__ b3) {
    extern __shared__ float sm[];
    float* xs  = sm;                 // 16*19   = 304
    float* y1s = xs + 304;           // 16*416  = 6656   (b, co*13+p)
    float* y2s = y1s + 6656;         // 16*448  = 7168   (b, ci*7+p)
    float* w1s = y2s + 7168;         // 224
    float* w2s = w1s + 224;          // 64*225  = 14400  (padded rows)
    float* w3c = w2s + 14400;        // 64*129  = 8256   (chunk: [ii][co], padded)

    const int t  = threadIdx.x;
    const int b0 = blockIdx.x * 16;

    for (int idx = t; idx < 16 * 19; idx += 256) xs[idx] = x[b0 * 19 + idx];
    for (int idx = t; idx < 224; idx += 256)     w1s[idx] = w1[idx];
    for (int idx = t; idx < 64 * 224; idx += 256) {
        int co = idx / 224, i = idx - co * 224;
        w2s[co * 225 + i] = w2[idx];
    }
    __syncthreads();

    // conv1 + ELU: [16,32,13]
    for (int idx = t; idx < 16 * 416; idx += 256) {
        int b = idx / 416, rem = idx - b * 416;
        int co = rem / 13, p = rem - co * 13;
        float s = b1[co];
#pragma unroll
        for (int k = 0; k < 7; k++) s += xs[b * 19 + p + k] * w1s[co * 7 + k];
        y1s[idx] = eluf(s);
    }
    __syncthreads();

    // conv2 + ELU: [16,64,7]. Units: (bg<4 x4b, cog<16 x4co, p<7) = 448, 4x4 register tile.
    for (int u = t; u < 448; u += 256) {
        int p = u % 7;
        int cog = (u / 7) & 15;
        int bg = u / 112;
        int bb0 = bg * 4, co0 = cog * 4;
        float acc[4][4];
#pragma unroll
        for (int a = 0; a < 4; a++)
#pragma unroll
            for (int c = 0; c < 4; c++) acc[a][c] = 0.0f;
        for (int ci = 0; ci < 32; ci++) {
            float yv[4][7];
#pragma unroll
            for (int a = 0; a < 4; a++)
#pragma unroll
                for (int k = 0; k < 7; k++)
                    yv[a][k] = y1s[(bb0 + a) * 416 + ci * 13 + p + k];
#pragma unroll
            for (int c = 0; c < 4; c++)
#pragma unroll
                for (int k = 0; k < 7; k++) {
                    float wv = w2s[(co0 + c) * 225 + ci * 7 + k];
#pragma unroll
                    for (int a = 0; a < 4; a++) acc[a][c] += yv[a][k] * wv;
                }
        }
#pragma unroll
        for (int a = 0; a < 4; a++)
#pragma unroll
            for (int c = 0; c < 4; c++) {
                float s = acc[a][c] + b2[co0 + c];
                y2s[(bb0 + a) * 448 + (co0 + c) * 7 + p] = eluf(s);
            }
    }
    __syncthreads();

    // conv3 + ELU -> feat[B,128]. 64 active threads: (cog<32 x4co, bg<2 x8b), K=448 in 7 chunks of 64.
    const int co0 = (t & 31) * 4;
    const int bgr = t >> 5;        // 0..7, active only <2
    const int bb0 = bgr * 8;
    float acc3[8][4];
#pragma unroll
    for (int a = 0; a < 8; a++)
#pragma unroll
        for (int c = 0; c < 4; c++) acc3[a][c] = 0.0f;

    for (int ch = 0; ch < 7; ch++) {
        int ic = ch * 64;
        __syncthreads();
        for (int idx = t; idx < 8192; idx += 256) {
            int co = idx >> 6, ii = idx & 63;
            w3c[ii * 129 + co] = w3[co * 448 + ic + ii];
        }
        __syncthreads();
        if (t < 64) {
#pragma unroll 4
            for (int ii = 0; ii < 64; ii++) {
                float wv0 = w3c[ii * 129 + co0 + 0];
                float wv1 = w3c[ii * 129 + co0 + 1];
                float wv2 = w3c[ii * 129 + co0 + 2];
                float wv3 = w3c[ii * 129 + co0 + 3];
#pragma unroll
                for (int a = 0; a < 8; a++) {
                    float yv = y2s[(bb0 + a) * 448 + ic + ii];
                    acc3[a][0] += yv * wv0;
                    acc3[a][1] += yv * wv1;
                    acc3[a][2] += yv * wv2;
                    acc3[a][3] += yv * wv3;
                }
            }
        }
    }
    if (t < 64) {
#pragma unroll
        for (int a = 0; a < 8; a++)
#pragma unroll
            for (int c = 0; c < 4; c++) {
                float s = acc3[a][c] + b3[co0 + c];
                g_feat[(size_t)(b0 + bb0 + a) * 128 + co0 + c] = eluf(s);
            }
    }
}

// ---------------- fused LSTM-cell GEMM (+optional head) ----------------
// Block: 256 threads, 32 rows x 512 gate-cols. Thread: j = t&127 owns gate
// quadruple {j, j+128, j+256, j+384}; rg = t>>7 owns 16 rows.
__launch_bounds__(256, 2)
__global__ void lstm_kernel(const float* __restrict__ A, int Ka,
                            const float* __restrict__ Wt, int WoffH,
                            const float* __restrict__ bias,
                            const float* __restrict__ Hprev,   // nullptr -> skip segment
                            const float* __restrict__ Cprev,   // nullptr -> zero
                            float* __restrict__ Hout, float* __restrict__ Cout,
                            const float* __restrict__ headW, const float* __restrict__ headB,
                            float* __restrict__ logits)        // nullptr -> no head
{
    __shared__ float Ws[16 * 512];
    __shared__ float Xs[16 * 33];

    const int t = threadIdx.x;
    const int j = t & 127;
    const int rg = t >> 7;
    const int row0 = blockIdx.x * 32;

    float acc[16][4];
#pragma unroll
    for (int r = 0; r < 16; r++)
#pragma unroll
        for (int g = 0; g < 4; g++) acc[r][g] = 0.0f;

    for (int seg = 0; seg < 2; seg++) {
        const float* S;
        int K, w0, srs;
        if (seg == 0) { S = A; K = Ka; w0 = 0; srs = Ka; }
        else { if (!Hprev) break; S = Hprev; K = 128; w0 = WoffH; srs = 128; }

        for (int kc = 0; kc < K; kc += 16) {
#pragma unroll
            for (int l = 0; l < 32; l++) {
                int idx = t + l * 256;
                Ws[idx] = Wt[(size_t)(w0 + kc + (idx >> 9)) * 512 + (idx & 511)];
            }
#pragma unroll
            for (int l = 0; l < 2; l++) {
                int idx = t + l * 256;
                int kk = idx & 15, r = idx >> 4;
                Xs[kk * 33 + r] = S[(size_t)(row0 + r) * srs + kc + kk];
            }
            __syncthreads();
#pragma unroll
            for (int kk = 0; kk < 16; kk++) {
                float w0v = Ws[kk * 512 + j];
                float w1v = Ws[kk * 512 + j + 128];
                float w2v = Ws[kk * 512 + j + 256];
                float w3v = Ws[kk * 512 + j + 384];
                const float* xp = &Xs[kk * 33 + rg * 16];
#pragma unroll
                for (int r = 0; r < 16; r++) {
                    float xv = xp[r];
                    acc[r][0] += xv * w0v;
                    acc[r][1] += xv * w1v;
                    acc[r][2] += xv * w2v;
                    acc[r][3] += xv * w3v;
                }
            }
            __syncthreads();
        }
    }

    // epilogue: LSTM cell
    float bi = bias[j], bf = bias[j + 128], bgv = bias[j + 256], bo = bias[j + 384];
    float hvals[16];
#pragma unroll
    for (int r = 0; r < 16; r++) {
        int row = row0 + rg * 16 + r;
        float gi = acc[r][0] + bi;
        float gf = acc[r][1] + bf;
        float gg = acc[r][2] + bgv;
        float go = acc[r][3] + bo;
        float cp = Cprev ? Cprev[(size_t)row * 128 + j] : 0.0f;
        float c = sigf(gf) * cp + sigf(gi) * tanhf(gg);
        float h = sigf(go) * tanhf(c);
        Cout[(size_t)row * 128 + j] = c;
        Hout[(size_t)row * 128 + j] = h;
        hvals[r] = h;
    }

    if (logits) {
        __syncthreads();              // done reading Ws; reuse as h-tile
        float* hs = Ws;               // 32*128 floats
#pragma unroll
        for (int r = 0; r < 16; r++) hs[(rg * 16 + r) * 128 + j] = hvals[r];
        __syncthreads();
        for (int idx = t; idx < 32 * 9; idx += 256) {
            int r = idx / 9, o = idx - r * 9;
            const float* hr = &hs[r * 128];
            const float* wr = &headW[o * 128];
            float s = headB[o];
#pragma unroll 8
            for (int jj = 0; jj < 128; jj++) s += hr[jj] * wr[jj];
            logits[(size_t)(row0 + r) * 9 + o] = s;
        }
    }
}

// ---------------- launch ----------------
extern "C" void kernel_launch(void* const* d_in, const int* in_sizes, int n_in,
                              void* d_out, int out_size) {
    const float* x        = (const float*)d_in[0];
    const float* ps       = (const float*)d_in[1];
    const float* conv1_w  = (const float*)d_in[2];
    const float* conv1_b  = (const float*)d_in[3];
    const float* conv2_w  = (const float*)d_in[4];
    const float* conv2_b  = (const float*)d_in[5];
    const float* conv3_w  = (const float*)d_in[6];
    const float* conv3_b  = (const float*)d_in[7];
    const float* w_ih1    = (const float*)d_in[8];
    const float* w_hh1    = (const float*)d_in[9];
    const float* b_ih1    = (const float*)d_in[10];
    const float* b_hh1    = (const float*)d_in[11];
    const float* w_ih2    = (const float*)d_in[12];
    const float* w_hh2    = (const float*)d_in[13];
    const float* b_ih2    = (const float*)d_in[14];
    const float* b_hh2    = (const float*)d_in[15];
    const float* head_w   = (const float*)d_in[16];
    const float* head_b   = (const float*)d_in[17];
    float* out = (float*)d_out;

    const int conv_smem = 37008 * 4;
    cudaFuncSetAttribute(conv_kernel, cudaFuncAttributeMaxDynamicSharedMemorySize, conv_smem);

    float *feat, *h1, *c1, *h2, *c2, *W1t, *W2t, *b1, *b2;
    cudaGetSymbolAddress((void**)&feat, g_feat);
    cudaGetSymbolAddress((void**)&h1, g_h1);
    cudaGetSymbolAddress((void**)&c1, g_c1);
    cudaGetSymbolAddress((void**)&h2, g_h2);
    cudaGetSymbolAddress((void**)&c2, g_c2);
    cudaGetSymbolAddress((void**)&W1t, g_W1t);
    cudaGetSymbolAddress((void**)&W2t, g_W2t);
    cudaGetSymbolAddress((void**)&b1, g_b1);
    cudaGetSymbolAddress((void**)&b2, g_b2);

    const int prep_total = 384 * 512 + 256 * 512 + 1024;
    prep_kernel<<<(prep_total + 255) / 256, 256>>>(w_ih1, w_hh1, b_ih1, b_hh1,
                                                   w_ih2, w_hh2, b_ih2, b_hh2);

    conv_kernel<<<Bn / 16, 256, conv_smem>>>(x, conv1_w, conv1_b, conv2_w, conv2_b,
                                             conv3_w, conv3_b);

    const int lstm_grid = Bn / 32;
    // step 0: input = [feat, zeros], h=c=0 for both layers
    lstm_kernel<<<lstm_grid, 256>>>(feat, 128, W1t, 256, b1,
                                    nullptr, nullptr, h1, c1,
                                    nullptr, nullptr, nullptr);
    lstm_kernel<<<lstm_grid, 256>>>(h1, 128, W2t, 128, b2,
                                    nullptr, nullptr, h2, c2,
                                    head_w, head_b, out);
    // steps 1..16
    for (int s = 1; s <= Tn; s++) {
        const float* A = ps + (size_t)(s - 1) * Bn * 256;
        lstm_kernel<<<lstm_grid, 256>>>(A, 256, W1t, 256, b1,
                                        h1, c1, h1, c1,
                                        nullptr, nullptr, nullptr);
        lstm_kernel<<<lstm_grid, 256>>>(h1, 128, W2t, 128, b2,
                                        h2, c2, h2, c2,
                                        head_w, head_b, out + (size_t)s * Bn * 9);
    }
}

// round 4
// speedup vs baseline: 2.7646x; 2.7646x over previous
#include <cuda_runtime.h>
#include <math.h>
#include <stdint.h>

#define Bn 32768
#define Tn 16

// ---------------- device scratch ----------------
__device__ float g_feat[Bn * 128];
__device__ float g_h1[Bn * 128];
__device__ float g_c1[Bn * 128];
__device__ float g_h2[Bn * 128];
__device__ float g_c2[Bn * 128];
__device__ float g_W1t[384 * 512];   // k-major [k][n], tf32-rounded
__device__ float g_W2t[256 * 512];   // k-major [k][n], tf32-rounded
__device__ float g_b1[512];
__device__ float g_b2[512];

// ---------------- helpers ----------------
__device__ __forceinline__ uint32_t smem_u32(const void* p) {
    uint32_t r;
    asm("{ .reg .u64 t; cvta.to.shared.u64 t, %1; cvt.u32.u64 %0, t; }" : "=r"(r) : "l"(p));
    return r;
}
#define CP16(dst, src) asm volatile("cp.async.cg.shared.global [%0], [%1], 16;" :: "r"(dst), "l"(src))
#define CP_COMMIT()    asm volatile("cp.async.commit_group;" ::: "memory")
#define CP_WAIT0()     asm volatile("cp.async.wait_group 0;" ::: "memory")
#define CP_WAIT1()     asm volatile("cp.async.wait_group 1;" ::: "memory")

#define MMA_TF32(d, a, b0v, b1v) \
    asm volatile("mma.sync.aligned.m16n8k8.row.col.f32.tf32.tf32.f32 " \
        "{%0,%1,%2,%3}, {%4,%5,%6,%7}, {%8,%9}, {%0,%1,%2,%3};" \
        : "+f"((d)[0]), "+f"((d)[1]), "+f"((d)[2]), "+f"((d)[3]) \
        : "r"((a)[0]), "r"((a)[1]), "r"((a)[2]), "r"((a)[3]), "r"(b0v), "r"(b1v))

__device__ __forceinline__ float to_tf32(float x) {
    uint32_t u;
    asm("cvt.rna.tf32.f32 %0, %1;" : "=r"(u) : "f"(x));
    return __uint_as_float(u);
}
__device__ __forceinline__ float sigf(float x) { return __fdividef(1.0f, 1.0f + __expf(-x)); }
__device__ __forceinline__ float tanhx(float x) { return __fdividef(2.0f, 1.0f + __expf(-2.0f * x)) - 1.0f; }
__device__ __forceinline__ float eluf(float x) { return x > 0.0f ? x : expm1f(x); }

// ---------------- weight prep: k-major transpose + tf32 round + bias fuse ----------------
__global__ void prep_kernel(const float* __restrict__ w_ih1, const float* __restrict__ w_hh1,
                            const float* __restrict__ b_ih1, const float* __restrict__ b_hh1,
                            const float* __restrict__ w_ih2, const float* __restrict__ w_hh2,
                            const float* __restrict__ b_ih2, const float* __restrict__ b_hh2) {
    int i = blockIdx.x * blockDim.x + threadIdx.x;
    const int total1 = 384 * 512;
    const int total2 = 256 * 512;
    if (i < total1) {
        int k = i >> 9, n = i & 511;
        float v = (k < 256) ? w_ih1[n * 256 + k] : w_hh1[n * 128 + (k - 256)];
        g_W1t[i] = to_tf32(v);
    } else if (i < total1 + total2) {
        int i2 = i - total1;
        int k = i2 >> 9, n = i2 & 511;
        float v = (k < 128) ? w_ih2[n * 128 + k] : w_hh2[n * 128 + (k - 128)];
        g_W2t[i2] = to_tf32(v);
    } else if (i < total1 + total2 + 512) {
        int n = i - total1 - total2;
        g_b1[n] = b_ih1[n] + b_hh1[n];
    } else if (i < total1 + total2 + 1024) {
        int n = i - total1 - total2 - 512;
        g_b2[n] = b_ih2[n] + b_hh2[n];
    }
}

// ---------------- fused conv stack: x[B,1,19] -> feat[B,128] ----------------
__launch_bounds__(256)
__global__ void conv_kernel(const float* __restrict__ x,
                            const float* __restrict__ w1, const float* __restrict__ b1,
                            const float* __restrict__ w2, const float* __restrict__ b2,
                            const float* __restrict__ w3, const float* __restrict__ b3) {
    extern __shared__ float sm[];
    float* xs  = sm;                 // 304
    float* y1s = xs + 304;           // 6656
    float* y2s = y1s + 6656;         // 7168
    float* w1s = y2s + 7168;         // 224
    float* w2s = w1s + 224;          // 14400
    float* w3c = w2s + 14400;        // 8256

    const int t  = threadIdx.x;
    const int b0 = blockIdx.x * 16;

    for (int idx = t; idx < 16 * 19; idx += 256) xs[idx] = x[b0 * 19 + idx];
    for (int idx = t; idx < 224; idx += 256)     w1s[idx] = w1[idx];
    for (int idx = t; idx < 64 * 224; idx += 256) {
        int co = idx / 224, i = idx - co * 224;
        w2s[co * 225 + i] = w2[idx];
    }
    __syncthreads();

    for (int idx = t; idx < 16 * 416; idx += 256) {
        int b = idx / 416, rem = idx - b * 416;
        int co = rem / 13, p = rem - co * 13;
        float s = b1[co];
#pragma unroll
        for (int k = 0; k < 7; k++) s += xs[b * 19 + p + k] * w1s[co * 7 + k];
        y1s[idx] = eluf(s);
    }
    __syncthreads();

    for (int u = t; u < 448; u += 256) {
        int p = u % 7;
        int cog = (u / 7) & 15;
        int bg = u / 112;
        int bb0 = bg * 4, co0 = cog * 4;
        float acc[4][4];
#pragma unroll
        for (int a = 0; a < 4; a++)
#pragma unroll
            for (int c = 0; c < 4; c++) acc[a][c] = 0.0f;
        for (int ci = 0; ci < 32; ci++) {
            float yv[4][7];
#pragma unroll
            for (int a = 0; a < 4; a++)
#pragma unroll
                for (int k = 0; k < 7; k++)
                    yv[a][k] = y1s[(bb0 + a) * 416 + ci * 13 + p + k];
#pragma unroll
            for (int c = 0; c < 4; c++)
#pragma unroll
                for (int k = 0; k < 7; k++) {
                    float wv = w2s[(co0 + c) * 225 + ci * 7 + k];
#pragma unroll
                    for (int a = 0; a < 4; a++) acc[a][c] += yv[a][k] * wv;
                }
        }
#pragma unroll
        for (int a = 0; a < 4; a++)
#pragma unroll
            for (int c = 0; c < 4; c++) {
                float s = acc[a][c] + b2[co0 + c];
                y2s[(bb0 + a) * 448 + (co0 + c) * 7 + p] = eluf(s);
            }
    }

    // conv3: 256 threads: (co0 = 4 cols, bb0 = 2 batch rows)
    const int co0 = (t & 31) * 4;
    const int bb0 = (t >> 5) * 2;
    float acc3[2][4];
#pragma unroll
    for (int a = 0; a < 2; a++)
#pragma unroll
        for (int c = 0; c < 4; c++) acc3[a][c] = 0.0f;

    for (int ch = 0; ch < 7; ch++) {
        int ic = ch * 64;
        __syncthreads();
        for (int idx = t; idx < 8192; idx += 256) {
            int co = idx >> 6, ii = idx & 63;
            w3c[ii * 129 + co] = w3[co * 448 + ic + ii];
        }
        __syncthreads();
#pragma unroll 4
        for (int ii = 0; ii < 64; ii++) {
            float wv0 = w3c[ii * 129 + co0 + 0];
            float wv1 = w3c[ii * 129 + co0 + 1];
            float wv2 = w3c[ii * 129 + co0 + 2];
            float wv3 = w3c[ii * 129 + co0 + 3];
#pragma unroll
            for (int a = 0; a < 2; a++) {
                float yv = y2s[(bb0 + a) * 448 + ic + ii];
                acc3[a][0] += yv * wv0;
                acc3[a][1] += yv * wv1;
                acc3[a][2] += yv * wv2;
                acc3[a][3] += yv * wv3;
            }
        }
    }
#pragma unroll
    for (int a = 0; a < 2; a++)
#pragma unroll
        for (int c = 0; c < 4; c++) {
            float s = acc3[a][c] + b3[co0 + c];
            g_feat[(size_t)(b0 + bb0 + a) * 128 + co0 + c] = eluf(s);
        }
}

// ---------------- tf32 mma.sync LSTM-cell GEMM ----------------
// SMEM (float words):
//   Bs double buf @0      : 2 * 32*520 = 33280   (k-major, 520-word rows)
//   As double buf @33280  : 2 * 4*64*12 = 6144   (per-k8tile, 12-word rows)
//   bias @39424 : 512
//   hw   @39936 : 1152    ([j][9])
// total 41088 words = 164352 B. Gate staging (64x516 = 33024) reuses Bs region.
#define SMEM_GEMM_WORDS 41088
#define SMEM_GEMM_BYTES (SMEM_GEMM_WORDS * 4)

__device__ __forceinline__ void load_chunk(int i, int tid, int row0,
    const float* A0, int lda0, int k0len, const float* A1, int lda1,
    const float* Wt, uint32_t smem_base)
{
    int kb = i << 5;
    const float* src; int ld; int col;
    if (kb < k0len) { src = A0; ld = lda0; col = kb; }
    else            { src = A1; ld = lda1; col = kb - k0len; }

    // A: 64 rows x 32 k = 512 x 16B, one per thread
    {
        int r = tid >> 3, q = tid & 7;
        uint32_t dst = smem_base +
            (33280u + (uint32_t)(i & 1) * 3072u + (uint32_t)(q >> 1) * 768u +
             (uint32_t)r * 12u + (uint32_t)(q & 1) * 4u) * 4u;
        CP16(dst, src + (size_t)(row0 + r) * ld + col + q * 4);
    }
    // B: 32 k-rows x 512 n = 4096 x 16B, 8 per thread
    const float* wsrc = Wt + (size_t)kb * 512;
#pragma unroll
    for (int it = 0; it < 8; it++) {
        int gidx = tid + it * 512;
        int kr = gidx >> 7, cq = gidx & 127;
        uint32_t dst = smem_base +
            ((uint32_t)(i & 1) * 16640u + (uint32_t)kr * 520u + (uint32_t)cq * 4u) * 4u;
        CP16(dst, wsrc + kr * 512 + cq * 4);
    }
    CP_COMMIT();
}

__global__ __launch_bounds__(512, 1)
void lstm_mma_kernel(const float* __restrict__ A0, int lda0, int k0len,
                     const float* __restrict__ A1, int lda1, int k1len,
                     const float* __restrict__ Wt,
                     const float* __restrict__ bias,
                     const float* __restrict__ Cprev,
                     float* __restrict__ Hout, float* __restrict__ Cout,
                     const float* __restrict__ headW, const float* __restrict__ headB,
                     float* __restrict__ logits)
{
    extern __shared__ float sm[];
    float* bias_s = sm + 39424;
    float* hw_s   = sm + 39936;
    uint32_t smem_base = smem_u32(sm);

    const int tid  = threadIdx.x;
    const int wid  = tid >> 5;
    const int lane = tid & 31;
    const int g    = lane >> 2;
    const int t4   = lane & 3;
    const int wm   = wid & 1;
    const int wn   = wid >> 1;
    const int row0 = blockIdx.x * 64;

    bias_s[tid & 511] = bias[tid & 511];
    if (logits) {
        for (int idx = tid; idx < 1152; idx += 512) {
            int j = idx / 9, o = idx - j * 9;
            hw_s[idx] = headW[o * 128 + j];
        }
    }
    __syncthreads();

    float acc[2][8][4];
#pragma unroll
    for (int mt = 0; mt < 2; mt++)
#pragma unroll
        for (int j8 = 0; j8 < 8; j8++)
#pragma unroll
            for (int q = 0; q < 4; q++) acc[mt][j8][q] = 0.0f;

    const int nch = (k0len + k1len) >> 5;
    load_chunk(0, tid, row0, A0, lda0, k0len, A1, lda1, Wt, smem_base);

    for (int i = 0; i < nch; i++) {
        if (i + 1 < nch) {
            load_chunk(i + 1, tid, row0, A0, lda0, k0len, A1, lda1, Wt, smem_base);
            CP_WAIT1();
        } else {
            CP_WAIT0();
        }
        __syncthreads();

        const float* Ab = sm + 33280 + (i & 1) * 3072;
        const float* Bb = sm + (i & 1) * 16640;

#pragma unroll
        for (int s = 0; s < 4; s++) {
            uint32_t a[2][4];
#pragma unroll
            for (int mt = 0; mt < 2; mt++) {
                const float* ap = Ab + s * 768 + (wm * 32 + mt * 16) * 12;
                a[mt][0] = __float_as_uint(ap[g * 12 + t4]);
                a[mt][1] = __float_as_uint(ap[(g + 8) * 12 + t4]);
                a[mt][2] = __float_as_uint(ap[g * 12 + t4 + 4]);
                a[mt][3] = __float_as_uint(ap[(g + 8) * 12 + t4 + 4]);
            }
            const float* bp0 = Bb + (s * 8 + t4) * 520 + wn * 64 + g;
#pragma unroll
            for (int j8 = 0; j8 < 8; j8++) {
                uint32_t b0 = __float_as_uint(bp0[j8 * 8]);
                uint32_t b1 = __float_as_uint(bp0[j8 * 8 + 4 * 520]);
                MMA_TF32(acc[0][j8], a[0], b0, b1);
                MMA_TF32(acc[1][j8], a[1], b0, b1);
            }
        }
        __syncthreads();
    }

    // ---- stage gates to smem [64][516] (reuses B buffers) ----
#pragma unroll
    for (int mt = 0; mt < 2; mt++) {
        int row = wm * 32 + mt * 16 + g;
#pragma unroll
        for (int j8 = 0; j8 < 8; j8++) {
            int col = wn * 64 + j8 * 8 + 2 * t4;
            sm[row * 516 + col]           = acc[mt][j8][0];
            sm[row * 516 + col + 1]       = acc[mt][j8][1];
            sm[(row + 8) * 516 + col]     = acc[mt][j8][2];
            sm[(row + 8) * 516 + col + 1] = acc[mt][j8][3];
        }
    }
    __syncthreads();

    // ---- LSTM cell epilogue: thread -> (j = tid&127, rows rg*16..+15) ----
    const int j  = tid & 127;
    const int rg = tid >> 7;
    const float bi = bias_s[j], bf = bias_s[128 + j], bg = bias_s[256 + j], bo = bias_s[384 + j];
#pragma unroll
    for (int rr = 0; rr < 16; rr++) {
        int r = rg * 16 + rr;
        int row = row0 + r;
        float gi = sm[r * 516 + j]       + bi;
        float gf = sm[r * 516 + 128 + j] + bf;
        float gg = sm[r * 516 + 256 + j] + bg;
        float go = sm[r * 516 + 384 + j] + bo;
        float cp = Cprev ? Cprev[(size_t)row * 128 + j] : 0.0f;
        float c  = sigf(gf) * cp + sigf(gi) * tanhx(gg);
        float h  = sigf(go) * tanhx(c);
        Cout[(size_t)row * 128 + j] = c;
        Hout[(size_t)row * 128 + j] = h;
        sm[r * 516 + j] = h;   // overwrite own gate-i slot for head stage
    }

    if (logits) {
        __syncthreads();
        for (int idx = tid; idx < 576; idx += 512) {
            int r = idx / 9, o = idx - r * 9;
            const float* hr = sm + r * 516;
            float ssum = headB[o];
#pragma unroll 8
            for (int jj = 0; jj < 128; jj++) ssum += hr[jj] * hw_s[jj * 9 + o];
            logits[(size_t)(row0 + r) * 9 + o] = ssum;
        }
    }
}

// ---------------- launch ----------------
extern "C" void kernel_launch(void* const* d_in, const int* in_sizes, int n_in,
                              void* d_out, int out_size) {
    const float* x        = (const float*)d_in[0];
    const float* ps       = (const float*)d_in[1];
    const float* conv1_w  = (const float*)d_in[2];
    const float* conv1_b  = (const float*)d_in[3];
    const float* conv2_w  = (const float*)d_in[4];
    const float* conv2_b  = (const float*)d_in[5];
    const float* conv3_w  = (const float*)d_in[6];
    const float* conv3_b  = (const float*)d_in[7];
    const float* w_ih1    = (const float*)d_in[8];
    const float* w_hh1    = (const float*)d_in[9];
    const float* b_ih1    = (const float*)d_in[10];
    const float* b_hh1    = (const float*)d_in[11];
    const float* w_ih2    = (const float*)d_in[12];
    const float* w_hh2    = (const float*)d_in[13];
    const float* b_ih2    = (const float*)d_in[14];
    const float* b_hh2    = (const float*)d_in[15];
    const float* head_w   = (const float*)d_in[16];
    const float* head_b   = (const float*)d_in[17];
    float* out = (float*)d_out;

    const int conv_smem = 37008 * 4;
    cudaFuncSetAttribute(conv_kernel, cudaFuncAttributeMaxDynamicSharedMemorySize, conv_smem);
    cudaFuncSetAttribute(lstm_mma_kernel, cudaFuncAttributeMaxDynamicSharedMemorySize, SMEM_GEMM_BYTES);

    float *feat, *h1, *c1, *h2, *c2, *W1t, *W2t, *b1, *b2;
    cudaGetSymbolAddress((void**)&feat, g_feat);
    cudaGetSymbolAddress((void**)&h1, g_h1);
    cudaGetSymbolAddress((void**)&c1, g_c1);
    cudaGetSymbolAddress((void**)&h2, g_h2);
    cudaGetSymbolAddress((void**)&c2, g_c2);
    cudaGetSymbolAddress((void**)&W1t, g_W1t);
    cudaGetSymbolAddress((void**)&W2t, g_W2t);
    cudaGetSymbolAddress((void**)&b1, g_b1);
    cudaGetSymbolAddress((void**)&b2, g_b2);

    const int prep_total = 384 * 512 + 256 * 512 + 1024;
    prep_kernel<<<(prep_total + 255) / 256, 256>>>(w_ih1, w_hh1, b_ih1, b_hh1,
                                                   w_ih2, w_hh2, b_ih2, b_hh2);

    conv_kernel<<<Bn / 16, 256, conv_smem>>>(x, conv1_w, conv1_b, conv2_w, conv2_b,
                                             conv3_w, conv3_b);

    const int grid = Bn / 64;
    // step 0: input = [feat, 0], h=c=0; only w_ih[:, :128] contributes for L1
    lstm_mma_kernel<<<grid, 512, SMEM_GEMM_BYTES>>>(
        feat, 128, 128, nullptr, 0, 0, W1t, b1,
        nullptr, h1, c1, head_w, head_b, nullptr);
    lstm_mma_kernel<<<grid, 512, SMEM_GEMM_BYTES>>>(
        h1, 128, 128, nullptr, 0, 0, W2t, b2,
        nullptr, h2, c2, head_w, head_b, out);
    // steps 1..16
    for (int s = 1; s <= Tn; s++) {
        const float* A = ps + (size_t)(s - 1) * Bn * 256;
        lstm_mma_kernel<<<grid, 512, SMEM_GEMM_BYTES>>>(
            A, 256, 256, h1, 128, 128, W1t, b1,
            c1, h1, c1, head_w, head_b, nullptr);
        lstm_mma_kernel<<<grid, 512, SMEM_GEMM_BYTES>>>(
            h1, 128, 128, h2, 128, 128, W2t, b2,
            c2, h2, c2, head_w, head_b, out + (size_t)s * Bn * 9);
    }
}

// round 5
// speedup vs baseline: 3.1115x; 1.1255x over previous
#include <cuda_runtime.h>
#include <math.h>
#include <stdint.h>

#define Bn 32768
#define Tn 16

// ---------------- device scratch ----------------
__device__ float g_feat[Bn * 128];
__device__ float g_h1[Bn * 128];
__device__ float g_c1[Bn * 128];
__device__ float g_h2[Bn * 128];
__device__ float g_c2[Bn * 128];
__device__ float g_W1p[12 * 16384];  // fragment-ordered, tf32-rounded
__device__ float g_W2p[8 * 16384];
__device__ float g_b1[512];
__device__ float g_b2[512];

// ---------------- helpers ----------------
__device__ __forceinline__ uint32_t smem_u32(const void* p) {
    uint32_t r;
    asm("{ .reg .u64 t; cvta.to.shared.u64 t, %1; cvt.u32.u64 %0, t; }" : "=r"(r) : "l"(p));
    return r;
}
#define CP16(dst, src) asm volatile("cp.async.cg.shared.global [%0], [%1], 16;" :: "r"(dst), "l"(src))
#define CP_COMMIT()    asm volatile("cp.async.commit_group;" ::: "memory")
#define CP_WAIT0()     asm volatile("cp.async.wait_group 0;" ::: "memory")
#define CP_WAIT1()     asm volatile("cp.async.wait_group 1;" ::: "memory")

#define MMA_TF32(d, a, b0v, b1v) \
    asm volatile("mma.sync.aligned.m16n8k8.row.col.f32.tf32.tf32.f32 " \
        "{%0,%1,%2,%3}, {%4,%5,%6,%7}, {%8,%9}, {%0,%1,%2,%3};" \
        : "+f"((d)[0]), "+f"((d)[1]), "+f"((d)[2]), "+f"((d)[3]) \
        : "r"((a)[0]), "r"((a)[1]), "r"((a)[2]), "r"((a)[3]), "r"(b0v), "r"(b1v))

__device__ __forceinline__ float to_tf32(float x) {
    uint32_t u;
    asm("cvt.rna.tf32.f32 %0, %1;" : "=r"(u) : "f"(x));
    return __uint_as_float(u);
}
__device__ __forceinline__ float sigf(float x) { return __fdividef(1.0f, 1.0f + __expf(-x)); }
__device__ __forceinline__ float tanhx(float x) { return __fdividef(2.0f, 1.0f + __expf(-2.0f * x)) - 1.0f; }
__device__ __forceinline__ float eluf(float x) { return x > 0.0f ? x : expm1f(x); }

// ---------------- weight prep: fragment-order permute + tf32 + bias fuse ----------------
// Fragment order per layer: [chunk][wn<8][s<4][j4<4][lane<32][w<4]
//   w: {b0(j8=2j4), b1(2j4), b0(2j4+1), b1(2j4+1)}; g=lane>>2, t4=lane&3
//   k = chunk*32 + s*8 + t4 + 4*(w&1); n = wn*64 + g + 8*(2*j4 + (w>>1))
__global__ void prep_kernel(const float* __restrict__ w_ih1, const float* __restrict__ w_hh1,
                            const float* __restrict__ b_ih1, const float* __restrict__ b_hh1,
                            const float* __restrict__ w_ih2, const float* __restrict__ w_hh2,
                            const float* __restrict__ b_ih2, const float* __restrict__ b_hh2) {
    int i = blockIdx.x * blockDim.x + threadIdx.x;
    const int total1 = 12 * 16384;
    const int total2 = 8 * 16384;
    if (i < total1 + total2) {
        int li = (i < total1) ? i : i - total1;
        int w    = li & 3;
        int lane = (li >> 2) & 31;
        int j4   = (li >> 7) & 3;
        int s    = (li >> 9) & 3;
        int wn   = (li >> 11) & 7;
        int ch   = li >> 14;
        int g = lane >> 2, t4 = lane & 3;
        int k = ch * 32 + s * 8 + t4 + 4 * (w & 1);
        int n = wn * 64 + g + 8 * (2 * j4 + (w >> 1));
        float v;
        if (i < total1) {
            v = (k < 256) ? w_ih1[n * 256 + k] : w_hh1[n * 128 + (k - 256)];
            g_W1p[li] = to_tf32(v);
        } else {
            v = (k < 128) ? w_ih2[n * 128 + k] : w_hh2[n * 128 + (k - 128)];
            g_W2p[li] = to_tf32(v);
        }
    } else if (i < total1 + total2 + 512) {
        int n = i - total1 - total2;
        g_b1[n] = b_ih1[n] + b_hh1[n];
    } else if (i < total1 + total2 + 1024) {
        int n = i - total1 - total2 - 512;
        g_b2[n] = b_ih2[n] + b_hh2[n];
    }
}

// ---------------- fused conv stack: x[B,1,19] -> feat[B,128] ----------------
__launch_bounds__(256)
__global__ void conv_kernel(const float* __restrict__ x,
                            const float* __restrict__ w1, const float* __restrict__ b1,
                            const float* __restrict__ w2, const float* __restrict__ b2,
                            const float* __restrict__ w3, const float* __restrict__ b3) {
    extern __shared__ float sm[];
    float* xs  = sm;                 // 304
    float* y1s = xs + 304;           // 6656
    float* y2s = y1s + 6656;         // 7168
    float* w1s = y2s + 7168;         // 224
    float* w2s = w1s + 224;          // 14400
    float* w3c = w2s + 14400;        // 8256

    const int t  = threadIdx.x;
    const int b0 = blockIdx.x * 16;

    for (int idx = t; idx < 16 * 19; idx += 256) xs[idx] = x[b0 * 19 + idx];
    for (int idx = t; idx < 224; idx += 256)     w1s[idx] = w1[idx];
    for (int idx = t; idx < 64 * 224; idx += 256) {
        int co = idx / 224, i = idx - co * 224;
        w2s[co * 225 + i] = w2[idx];
    }
    __syncthreads();

    for (int idx = t; idx < 16 * 416; idx += 256) {
        int b = idx / 416, rem = idx - b * 416;
        int co = rem / 13, p = rem - co * 13;
        float s = b1[co];
#pragma unroll
        for (int k = 0; k < 7; k++) s += xs[b * 19 + p + k] * w1s[co * 7 + k];
        y1s[idx] = eluf(s);
    }
    __syncthreads();

    for (int u = t; u < 448; u += 256) {
        int p = u % 7;
        int cog = (u / 7) & 15;
        int bg = u / 112;
        int bb0 = bg * 4, co0 = cog * 4;
        float acc[4][4];
#pragma unroll
        for (int a = 0; a < 4; a++)
#pragma unroll
            for (int c = 0; c < 4; c++) acc[a][c] = 0.0f;
        for (int ci = 0; ci < 32; ci++) {
            float yv[4][7];
#pragma unroll
            for (int a = 0; a < 4; a++)
#pragma unroll
                for (int k = 0; k < 7; k++)
                    yv[a][k] = y1s[(bb0 + a) * 416 + ci * 13 + p + k];
#pragma unroll
            for (int c = 0; c < 4; c++)
#pragma unroll
                for (int k = 0; k < 7; k++) {
                    float wv = w2s[(co0 + c) * 225 + ci * 7 + k];
#pragma unroll
                    for (int a = 0; a < 4; a++) acc[a][c] += yv[a][k] * wv;
                }
        }
#pragma unroll
        for (int a = 0; a < 4; a++)
#pragma unroll
            for (int c = 0; c < 4; c++) {
                float s = acc[a][c] + b2[co0 + c];
                y2s[(bb0 + a) * 448 + (co0 + c) * 7 + p] = eluf(s);
            }
    }

    const int co0 = (t & 31) * 4;
    const int bb0 = (t >> 5) * 2;
    float acc3[2][4];
#pragma unroll
    for (int a = 0; a < 2; a++)
#pragma unroll
        for (int c = 0; c < 4; c++) acc3[a][c] = 0.0f;

    for (int ch = 0; ch < 7; ch++) {
        int ic = ch * 64;
        __syncthreads();
        for (int idx = t; idx < 8192; idx += 256) {
            int co = idx >> 6, ii = idx & 63;
            w3c[ii * 129 + co] = w3[co * 448 + ic + ii];
        }
        __syncthreads();
#pragma unroll 4
        for (int ii = 0; ii < 64; ii++) {
            float wv0 = w3c[ii * 129 + co0 + 0];
            float wv1 = w3c[ii * 129 + co0 + 1];
            float wv2 = w3c[ii * 129 + co0 + 2];
            float wv3 = w3c[ii * 129 + co0 + 3];
#pragma unroll
            for (int a = 0; a < 2; a++) {
                float yv = y2s[(bb0 + a) * 448 + ic + ii];
                acc3[a][0] += yv * wv0;
                acc3[a][1] += yv * wv1;
                acc3[a][2] += yv * wv2;
                acc3[a][3] += yv * wv3;
            }
        }
    }
#pragma unroll
    for (int a = 0; a < 2; a++)
#pragma unroll
        for (int c = 0; c < 4; c++) {
            float s = acc3[a][c] + b3[co0 + c];
            g_feat[(size_t)(b0 + bb0 + a) * 128 + co0 + c] = eluf(s);
        }
}

// ---------------- tf32 mma.sync LSTM-cell GEMM ----------------
// SMEM words: B[3][16384] @0, A[3][2048] @49152, bias @55296, hw @55808.
// Total 56960 words = 227840 B. Gate staging (64x516) reuses B buffers.
#define SMEM_GEMM_WORDS 56960
#define SMEM_GEMM_BYTES (SMEM_GEMM_WORDS * 4)

__device__ __forceinline__ void load_chunk(int i, int tid, int row0,
    const float* A0, int lda0, int k0len, const float* A1, int lda1,
    const float* Wp, uint32_t smem_base)
{
    const int buf = i % 3;
    // B: linear 16384-word copy, fragment-ordered in gmem
    const float* wsrc = Wp + (size_t)i * 16384;
    uint32_t bbase = smem_base + (uint32_t)buf * 65536u;
#pragma unroll
    for (int it = 0; it < 8; it++) {
        uint32_t off = (uint32_t)(it * 512 + tid) * 16u;
        CP16(bbase + off, wsrc + (size_t)(it * 512 + tid) * 4);
    }
    // A: 64 rows x 32 k, XOR-swizzled
    int kb = i << 5;
    const float* src; int ld; int col;
    if (kb < k0len) { src = A0; ld = lda0; col = kb; }
    else            { src = A1; ld = lda1; col = kb - k0len; }
    {
        int r = tid >> 3, q = tid & 7;
        uint32_t word = 49152u + (uint32_t)buf * 2048u +
                        (uint32_t)(r * 32) + (uint32_t)((4 * q) ^ (4 * (r & 7)));
        CP16(smem_base + word * 4u, src + (size_t)(row0 + r) * ld + col + q * 4);
    }
    CP_COMMIT();
}

__global__ __launch_bounds__(512, 1)
void lstm_mma_kernel(const float* __restrict__ A0, int lda0, int k0len,
                     const float* __restrict__ A1, int lda1, int k1len,
                     const float* __restrict__ Wp,
                     const float* __restrict__ bias,
                     const float* __restrict__ Cprev,
                     float* __restrict__ Hout, float* __restrict__ Cout,
                     const float* __restrict__ headW, const float* __restrict__ headB,
                     float* __restrict__ logits)
{
    extern __shared__ float sm[];
    float* bias_s = sm + 55296;
    float* hw_s   = sm + 55808;
    uint32_t smem_base = smem_u32(sm);

    const int tid  = threadIdx.x;
    const int wid  = tid >> 5;
    const int lane = tid & 31;
    const int g    = lane >> 2;
    const int t4   = lane & 3;
    const int wm   = wid & 1;
    const int wn   = wid >> 1;
    const int row0 = blockIdx.x * 64;

    bias_s[tid] = bias[tid];
    if (logits) {
        for (int idx = tid; idx < 1152; idx += 512) {
            int j = idx / 9, o = idx - j * 9;
            hw_s[idx] = headW[o * 128 + j];
        }
    }
    __syncthreads();

    float acc[2][8][4];
#pragma unroll
    for (int mt = 0; mt < 2; mt++)
#pragma unroll
        for (int j8 = 0; j8 < 8; j8++)
#pragma unroll
            for (int q = 0; q < 4; q++) acc[mt][j8][q] = 0.0f;

    const int nch = (k0len + k1len) >> 5;
    load_chunk(0, tid, row0, A0, lda0, k0len, A1, lda1, Wp, smem_base);
    load_chunk(1, tid, row0, A0, lda0, k0len, A1, lda1, Wp, smem_base);

    for (int i = 0; i < nch; i++) {
        if (i < nch - 1) { CP_WAIT1(); } else { CP_WAIT0(); }
        __syncthreads();
        if (i + 2 < nch)
            load_chunk(i + 2, tid, row0, A0, lda0, k0len, A1, lda1, Wp, smem_base);

        const int buf = i % 3;
        const float*  Ab = sm + 49152 + buf * 2048;
        const float4* Bq = (const float4*)(sm + buf * 16384 + wn * 2048);

#pragma unroll
        for (int s = 0; s < 4; s++) {
            // B fragments: 4x LDS.128, fragment order
            float4 bv[4];
#pragma unroll
            for (int j4 = 0; j4 < 4; j4++) bv[j4] = Bq[(s * 4 + j4) * 32 + lane];
            // A fragments: 8x LDS.32 from swizzled layout
            uint32_t a[2][4];
#pragma unroll
            for (int mt = 0; mt < 2; mt++) {
                int r0 = wm * 32 + mt * 16 + g;
                int kw0 = (8 * s + t4) ^ (4 * g);
                int kw1 = (8 * s + t4 + 4) ^ (4 * g);
                a[mt][0] = __float_as_uint(Ab[r0 * 32 + kw0]);
                a[mt][1] = __float_as_uint(Ab[(r0 + 8) * 32 + kw0]);
                a[mt][2] = __float_as_uint(Ab[r0 * 32 + kw1]);
                a[mt][3] = __float_as_uint(Ab[(r0 + 8) * 32 + kw1]);
            }
#pragma unroll
            for (int j4 = 0; j4 < 4; j4++) {
                uint32_t b0e = __float_as_uint(bv[j4].x);
                uint32_t b1e = __float_as_uint(bv[j4].y);
                uint32_t b0o = __float_as_uint(bv[j4].z);
                uint32_t b1o = __float_as_uint(bv[j4].w);
                MMA_TF32(acc[0][2 * j4],     a[0], b0e, b1e);
                MMA_TF32(acc[1][2 * j4],     a[1], b0e, b1e);
                MMA_TF32(acc[0][2 * j4 + 1], a[0], b0o, b1o);
                MMA_TF32(acc[1][2 * j4 + 1], a[1], b0o, b1o);
            }
        }
    }
    __syncthreads();

    // ---- stage gates to smem [64][516] (reuses B buffers) ----
#pragma unroll
    for (int mt = 0; mt < 2; mt++) {
        int row = wm * 32 + mt * 16 + g;
#pragma unroll
        for (int j8 = 0; j8 < 8; j8++) {
            int col = wn * 64 + j8 * 8 + 2 * t4;
            sm[row * 516 + col]           = acc[mt][j8][0];
            sm[row * 516 + col + 1]       = acc[mt][j8][1];
            sm[(row + 8) * 516 + col]     = acc[mt][j8][2];
            sm[(row + 8) * 516 + col + 1] = acc[mt][j8][3];
        }
    }
    __syncthreads();

    // ---- LSTM cell epilogue ----
    const int j  = tid & 127;
    const int rg = tid >> 7;
    const float bi = bias_s[j], bf = bias_s[128 + j], bg = bias_s[256 + j], bo = bias_s[384 + j];
#pragma unroll
    for (int rr = 0; rr < 16; rr++) {
        int r = rg * 16 + rr;
        int row = row0 + r;
        float gi = sm[r * 516 + j]       + bi;
        float gf = sm[r * 516 + 128 + j] + bf;
        float gg = sm[r * 516 + 256 + j] + bg;
        float go = sm[r * 516 + 384 + j] + bo;
        float cp = Cprev ? Cprev[(size_t)row * 128 + j] : 0.0f;
        float c  = sigf(gf) * cp + sigf(gi) * tanhx(gg);
        float h  = sigf(go) * tanhx(c);
        Cout[(size_t)row * 128 + j] = c;
        Hout[(size_t)row * 128 + j] = h;
        sm[r * 516 + j] = h;
    }

    if (logits) {
        __syncthreads();
        for (int idx = tid; idx < 576; idx += 512) {
            int r = idx / 9, o = idx - r * 9;
            const float* hr = sm + r * 516;
            float ssum = headB[o];
#pragma unroll 8
            for (int jj = 0; jj < 128; jj++) ssum += hr[jj] * hw_s[jj * 9 + o];
            logits[(size_t)(row0 + r) * 9 + o] = ssum;
        }
    }
}

// ---------------- launch ----------------
extern "C" void kernel_launch(void* const* d_in, const int* in_sizes, int n_in,
                              void* d_out, int out_size) {
    const float* x        = (const float*)d_in[0];
    const float* ps       = (const float*)d_in[1];
    const float* conv1_w  = (const float*)d_in[2];
    const float* conv1_b  = (const float*)d_in[3];
    const float* conv2_w  = (const float*)d_in[4];
    const float* conv2_b  = (const float*)d_in[5];
    const float* conv3_w  = (const float*)d_in[6];
    const float* conv3_b  = (const float*)d_in[7];
    const float* w_ih1    = (const float*)d_in[8];
    const float* w_hh1    = (const float*)d_in[9];
    const float* b_ih1    = (const float*)d_in[10];
    const float* b_hh1    = (const float*)d_in[11];
    const float* w_ih2    = (const float*)d_in[12];
    const float* w_hh2    = (const float*)d_in[13];
    const float* b_ih2    = (const float*)d_in[14];
    const float* b_hh2    = (const float*)d_in[15];
    const float* head_w   = (const float*)d_in[16];
    const float* head_b   = (const float*)d_in[17];
    float* out = (float*)d_out;

    const int conv_smem = 37008 * 4;
    cudaFuncSetAttribute(conv_kernel, cudaFuncAttributeMaxDynamicSharedMemorySize, conv_smem);
    cudaFuncSetAttribute(lstm_mma_kernel, cudaFuncAttributeMaxDynamicSharedMemorySize, SMEM_GEMM_BYTES);

    float *feat, *h1, *c1, *h2, *c2, *W1p, *W2p, *b1, *b2;
    cudaGetSymbolAddress((void**)&feat, g_feat);
    cudaGetSymbolAddress((void**)&h1, g_h1);
    cudaGetSymbolAddress((void**)&c1, g_c1);
    cudaGetSymbolAddress((void**)&h2, g_h2);
    cudaGetSymbolAddress((void**)&c2, g_c2);
    cudaGetSymbolAddress((void**)&W1p, g_W1p);
    cudaGetSymbolAddress((void**)&W2p, g_W2p);
    cudaGetSymbolAddress((void**)&b1, g_b1);
    cudaGetSymbolAddress((void**)&b2, g_b2);

    const int prep_total = 12 * 16384 + 8 * 16384 + 1024;
    prep_kernel<<<(prep_total + 255) / 256, 256>>>(w_ih1, w_hh1, b_ih1, b_hh1,
                                                   w_ih2, w_hh2, b_ih2, b_hh2);

    conv_kernel<<<Bn / 16, 256, conv_smem>>>(x, conv1_w, conv1_b, conv2_w, conv2_b,
                                             conv3_w, conv3_b);

    const int grid = Bn / 64;
    // step 0: input = [feat, 0], h=c=0; k>=128 contributes nothing for L1
    lstm_mma_kernel<<<grid, 512, SMEM_GEMM_BYTES>>>(
        feat, 128, 128, nullptr, 0, 0, W1p, b1,
        nullptr, h1, c1, head_w, head_b, nullptr);
    lstm_mma_kernel<<<grid, 512, SMEM_GEMM_BYTES>>>(
        h1, 128, 128, nullptr, 0, 0, W2p, b2,
        nullptr, h2, c2, head_w, head_b, out);
    // steps 1..16
    for (int s = 1; s <= Tn; s++) {
        const float* A = ps + (size_t)(s - 1) * Bn * 256;
        lstm_mma_kernel<<<grid, 512, SMEM_GEMM_BYTES>>>(
            A, 256, 256, h1, 128, 128, W1p, b1,
            c1, h1, c1, head_w, head_b, nullptr);
        lstm_mma_kernel<<<grid, 512, SMEM_GEMM_BYTES>>>(
            h1, 128, 128, h2, 128, 128, W2p, b2,
            c2, h2, c2, head_w, head_b, out + (size_t)s * Bn * 9);
    }
}